// round 3
// baseline (speedup 1.0000x reference)
#include <cuda_runtime.h>
#include <cuda_bf16.h>
#include <math.h>
#include <stdint.h>

// Problem constants
#define BB 8
#define SS 1024
#define DD 512
#define HH 8
#define UU 64
#define FF 2048
#define LN_EPS 1e-3f

// ---------------- scratch (device globals; no allocation allowed) ----------
__device__ float g_q[HH * BB * SS * UU];            // [H,B,S,U]
__device__ float g_kT[HH * BB * UU * SS];           // [H,B,U,S]
__device__ float g_v[HH * BB * SS * DD];            // [H,B,S,D]
__device__ float g_scores[(size_t)HH * BB * SS * SS];  // [H,B,S,S]
__device__ float g_concat[BB * SS * (HH * DD)];     // [B,S,H*D]
__device__ float g_tmp[BB * SS * DD];               // mha out, then ff2 out
__device__ float g_h[BB * SS * DD];                 // LN1 output
__device__ float g_ff[BB * SS * FF];                // relu(ff1)

// ---------------- tf32 tensor-core batched strided GEMM ---------------------
// C[z][m,n] = alpha * sum_k A[z][m,k]*B[z][k,n] (+bias[n]) (+relu)
// Assumes: A k-contiguous, B n-contiguous, M % 128 == 0, K % 16 == 0,
//          sAm % 4 == 0, sBk % 4 == 0.  N guarded (multiple of 4).
#define BM 128
#define BN 128
#define BK 16
#define AKP 20    // A smem k-stride   (As[m][k'], conflict-free frag loads)
#define BNP 136   // B smem n-stride   (Bs[k][n'], conflict-free STS.128 + frag loads)

__device__ __forceinline__ uint32_t f2tf32(float x) {
    uint32_t y;
    asm("cvt.rna.tf32.f32 %0, %1;" : "=r"(y) : "f"(x));
    return y;
}

__device__ __forceinline__ void mma_tf32(float* c, const uint32_t* a, const uint32_t* b) {
    asm volatile(
        "mma.sync.aligned.m16n8k8.row.col.f32.tf32.tf32.f32 "
        "{%0,%1,%2,%3}, {%4,%5,%6,%7}, {%8,%9}, {%0,%1,%2,%3};\n"
        : "+f"(c[0]), "+f"(c[1]), "+f"(c[2]), "+f"(c[3])
        : "r"(a[0]), "r"(a[1]), "r"(a[2]), "r"(a[3]), "r"(b[0]), "r"(b[1]));
}

__global__ __launch_bounds__(256)
void gemm_tc(const float* __restrict__ A, const float* __restrict__ B,
             float* __restrict__ C, const float* __restrict__ bias,
             int M, int N, int K,
             int sAm, int sBk, int sCm, int sCn,
             int HD, int sA1, int sA2, int sB1, int sB2, int sC1, int sC2,
             float alpha, int relu)
{
    const int z = blockIdx.z;
    A += (size_t)(z / HD) * sA1 + (size_t)(z % HD) * sA2;
    B += (size_t)(z / HD) * sB1 + (size_t)(z % HD) * sB2;
    C += (size_t)(z / HD) * sC1 + (size_t)(z % HD) * sC2;

    const int row0 = blockIdx.y * BM;
    const int col0 = blockIdx.x * BN;
    const int tid  = threadIdx.x;
    const int w    = tid >> 5;
    const int lane = tid & 31;
    const int wm   = w & 1;          // 2 warps over M (64 rows each)
    const int wn   = w >> 1;         // 4 warps over N (32 cols each)
    const int r    = lane >> 2;      // 0..7
    const int cq   = lane & 3;       // 0..3

    __shared__ uint32_t As[2][BM][AKP];
    __shared__ uint32_t Bs[2][BK][BNP];

    float acc[4][4][4];
#pragma unroll
    for (int i = 0; i < 4; i++)
#pragma unroll
        for (int j = 0; j < 4; j++)
#pragma unroll
            for (int q = 0; q < 4; q++) acc[i][j][q] = 0.f;

    // ---- global pointers (float4 granularity) ----
    const int rowA = tid >> 2;          // 0..63  (plus +64 for second half)
    const int kqA  = (tid & 3) * 4;     // k offset within tile
    const int browB = tid >> 5;         // 0..7   (plus +8 for second half)
    const int nqB   = (tid & 31) * 4;   // n offset within tile
    const bool okn  = (col0 + nqB) < N;

    const float* pA0 = A + (size_t)(row0 + rowA) * sAm + kqA;
    const float* pA1 = pA0 + (size_t)64 * sAm;
    const float* pB0 = B + (size_t)browB * sBk + col0 + nqB;
    const float* pB1 = pB0 + (size_t)8 * sBk;

    float4 a4[2], b4[2];
    const float4 z4 = make_float4(0.f, 0.f, 0.f, 0.f);

    // ---- load tile 0 ----
    a4[0] = *(const float4*)(pA0);
    a4[1] = *(const float4*)(pA1);
    b4[0] = okn ? *(const float4*)(pB0) : z4;
    b4[1] = okn ? *(const float4*)(pB1) : z4;

    {
        As[0][rowA][kqA + 0]      = f2tf32(a4[0].x);
        As[0][rowA][kqA + 1]      = f2tf32(a4[0].y);
        As[0][rowA][kqA + 2]      = f2tf32(a4[0].z);
        As[0][rowA][kqA + 3]      = f2tf32(a4[0].w);
        As[0][rowA + 64][kqA + 0] = f2tf32(a4[1].x);
        As[0][rowA + 64][kqA + 1] = f2tf32(a4[1].y);
        As[0][rowA + 64][kqA + 2] = f2tf32(a4[1].z);
        As[0][rowA + 64][kqA + 3] = f2tf32(a4[1].w);
        uint4 u0 = make_uint4(f2tf32(b4[0].x), f2tf32(b4[0].y), f2tf32(b4[0].z), f2tf32(b4[0].w));
        uint4 u1 = make_uint4(f2tf32(b4[1].x), f2tf32(b4[1].y), f2tf32(b4[1].z), f2tf32(b4[1].w));
        *(uint4*)&Bs[0][browB][nqB]     = u0;
        *(uint4*)&Bs[0][browB + 8][nqB] = u1;
    }
    __syncthreads();

    int cur = 0;
    for (int k0 = 0; k0 < K; k0 += BK) {
        const bool nxt = (k0 + BK) < K;
        if (nxt) {
            a4[0] = *(const float4*)(pA0 + k0 + BK);
            a4[1] = *(const float4*)(pA1 + k0 + BK);
            const float* qB0 = pB0 + (size_t)(k0 + BK) * sBk;
            const float* qB1 = pB1 + (size_t)(k0 + BK) * sBk;
            b4[0] = okn ? *(const float4*)(qB0) : z4;
            b4[1] = okn ? *(const float4*)(qB1) : z4;
        }

        // ---- compute from smem buffer `cur` ----
#pragma unroll
        for (int k8 = 0; k8 < BK; k8 += 8) {
            uint32_t af[4][4];
            uint32_t bf[4][2];
#pragma unroll
            for (int mt = 0; mt < 4; mt++) {
                const int row = wm * 64 + mt * 16 + r;
                af[mt][0] = As[cur][row][k8 + cq];
                af[mt][1] = As[cur][row + 8][k8 + cq];
                af[mt][2] = As[cur][row][k8 + cq + 4];
                af[mt][3] = As[cur][row + 8][k8 + cq + 4];
            }
#pragma unroll
            for (int nt = 0; nt < 4; nt++) {
                const int col = wn * 32 + nt * 8 + r;
                bf[nt][0] = Bs[cur][k8 + cq][col];
                bf[nt][1] = Bs[cur][k8 + cq + 4][col];
            }
#pragma unroll
            for (int mt = 0; mt < 4; mt++)
#pragma unroll
                for (int nt = 0; nt < 4; nt++)
                    mma_tf32(acc[mt][nt], af[mt], bf[nt]);
        }

        if (nxt) {
            const int nb = cur ^ 1;
            As[nb][rowA][kqA + 0]      = f2tf32(a4[0].x);
            As[nb][rowA][kqA + 1]      = f2tf32(a4[0].y);
            As[nb][rowA][kqA + 2]      = f2tf32(a4[0].z);
            As[nb][rowA][kqA + 3]      = f2tf32(a4[0].w);
            As[nb][rowA + 64][kqA + 0] = f2tf32(a4[1].x);
            As[nb][rowA + 64][kqA + 1] = f2tf32(a4[1].y);
            As[nb][rowA + 64][kqA + 2] = f2tf32(a4[1].z);
            As[nb][rowA + 64][kqA + 3] = f2tf32(a4[1].w);
            uint4 u0 = make_uint4(f2tf32(b4[0].x), f2tf32(b4[0].y), f2tf32(b4[0].z), f2tf32(b4[0].w));
            uint4 u1 = make_uint4(f2tf32(b4[1].x), f2tf32(b4[1].y), f2tf32(b4[1].z), f2tf32(b4[1].w));
            *(uint4*)&Bs[nb][browB][nqB]     = u0;
            *(uint4*)&Bs[nb][browB + 8][nqB] = u1;
            cur = nb;
            __syncthreads();
        }
    }

    // ---- epilogue ----
#pragma unroll
    for (int mt = 0; mt < 4; mt++) {
        const int rr0 = row0 + wm * 64 + mt * 16 + r;
        const int rr1 = rr0 + 8;
#pragma unroll
        for (int nt = 0; nt < 4; nt++) {
            const int cc0 = col0 + wn * 32 + nt * 8 + 2 * cq;
            const int cc1 = cc0 + 1;
            if (cc0 < N) {
                float v0 = acc[mt][nt][0] * alpha;
                float v2 = acc[mt][nt][2] * alpha;
                if (bias) { v0 += bias[cc0]; v2 += bias[cc0]; }
                if (relu) { v0 = fmaxf(v0, 0.f); v2 = fmaxf(v2, 0.f); }
                C[(size_t)rr0 * sCm + (size_t)cc0 * sCn] = v0;
                C[(size_t)rr1 * sCm + (size_t)cc0 * sCn] = v2;
            }
            if (cc1 < N) {
                float v1 = acc[mt][nt][1] * alpha;
                float v3 = acc[mt][nt][3] * alpha;
                if (bias) { v1 += bias[cc1]; v3 += bias[cc1]; }
                if (relu) { v1 = fmaxf(v1, 0.f); v3 = fmaxf(v3, 0.f); }
                C[(size_t)rr0 * sCm + (size_t)cc1 * sCn] = v1;
                C[(size_t)rr1 * sCm + (size_t)cc1 * sCn] = v3;
            }
        }
    }
}

// ---------------- softmax over rows of length 1024 --------------------------
__global__ __launch_bounds__(256)
void softmax_k(float* __restrict__ S)
{
    float4* p = (float4*)(S + (size_t)blockIdx.x * 1024);
    const int t = threadIdx.x;
    const int lane = t & 31, wid = t >> 5;
    __shared__ float red[8];

    float4 v = p[t];
    float m = fmaxf(fmaxf(v.x, v.y), fmaxf(v.z, v.w));
#pragma unroll
    for (int s = 16; s > 0; s >>= 1) m = fmaxf(m, __shfl_xor_sync(0xffffffffu, m, s));
    if (lane == 0) red[wid] = m;
    __syncthreads();
    m = red[lane & 7];
#pragma unroll
    for (int s = 4; s > 0; s >>= 1) m = fmaxf(m, __shfl_xor_sync(0xffffffffu, m, s));
    m = __shfl_sync(0xffffffffu, m, 0);

    v.x = __expf(v.x - m); v.y = __expf(v.y - m);
    v.z = __expf(v.z - m); v.w = __expf(v.w - m);
    float sum = v.x + v.y + v.z + v.w;
#pragma unroll
    for (int s = 16; s > 0; s >>= 1) sum += __shfl_xor_sync(0xffffffffu, sum, s);
    __syncthreads();
    if (lane == 0) red[wid] = sum;
    __syncthreads();
    sum = red[lane & 7];
#pragma unroll
    for (int s = 4; s > 0; s >>= 1) sum += __shfl_xor_sync(0xffffffffu, sum, s);
    sum = __shfl_sync(0xffffffffu, sum, 0);

    float inv = 1.f / sum;
    v.x *= inv; v.y *= inv; v.z *= inv; v.w *= inv;
    p[t] = v;
}

// ---------------- residual + layernorm (rows of 512) ------------------------
__global__ __launch_bounds__(256)
void ln_k(float* __restrict__ out, const float* __restrict__ a,
          const float* __restrict__ b, const float* __restrict__ gamma,
          const float* __restrict__ beta)
{
    size_t base = (size_t)blockIdx.x * DD;
    int t = threadIdx.x;
    float x0 = a[base + t]       + b[base + t];
    float x1 = a[base + t + 256] + b[base + t + 256];

    __shared__ float r1[256], r2[256];
    r1[t] = x0 + x1;
    r2[t] = x0 * x0 + x1 * x1;
    __syncthreads();
    for (int s = 128; s > 0; s >>= 1) {
        if (t < s) { r1[t] += r1[t + s]; r2[t] += r2[t + s]; }
        __syncthreads();
    }
    float mean = r1[0] * (1.f / DD);
    float var  = r2[0] * (1.f / DD) - mean * mean;
    float rstd = rsqrtf(var + LN_EPS);

    out[base + t]       = gamma[t]       * (x0 - mean) * rstd + beta[t];
    out[base + t + 256] = gamma[t + 256] * (x1 - mean) * rstd + beta[t + 256];
}

// ---------------- host side --------------------------------------------------
static void gemm(const float* A, const float* B, float* C, const float* bias,
                 int M, int N, int K, int nb, int HD,
                 int sAm, int sBk, int sCm, int sCn,
                 int sA1, int sA2, int sB1, int sB2, int sC1, int sC2,
                 float alpha, int relu)
{
    dim3 grid((N + BN - 1) / BN, (M + BM - 1) / BM, nb);
    gemm_tc<<<grid, 256>>>(A, B, C, bias, M, N, K,
                           sAm, sBk, sCm, sCn,
                           HD, sA1, sA2, sB1, sB2, sC1, sC2, alpha, relu);
}

extern "C" void kernel_launch(void* const* d_in, const int* in_sizes, int n_in,
                              void* d_out, int out_size)
{
    const float* x      = (const float*)d_in[0];
    const float* qw     = (const float*)d_in[1];
    const float* kw     = (const float*)d_in[2];
    const float* vw     = (const float*)d_in[3];
    const float* lw     = (const float*)d_in[4];
    const float* gamma1 = (const float*)d_in[5];
    const float* beta1  = (const float*)d_in[6];
    const float* w1     = (const float*)d_in[7];
    const float* b1     = (const float*)d_in[8];
    const float* w2     = (const float*)d_in[9];
    const float* b2     = (const float*)d_in[10];
    const float* gamma2 = (const float*)d_in[11];
    const float* beta2  = (const float*)d_in[12];
    float* out = (float*)d_out;

    float *q, *kT, *v, *scores, *concat, *tmp, *h, *ff;
    cudaGetSymbolAddress((void**)&q,      g_q);
    cudaGetSymbolAddress((void**)&kT,     g_kT);
    cudaGetSymbolAddress((void**)&v,      g_v);
    cudaGetSymbolAddress((void**)&scores, g_scores);
    cudaGetSymbolAddress((void**)&concat, g_concat);
    cudaGetSymbolAddress((void**)&tmp,    g_tmp);
    cudaGetSymbolAddress((void**)&h,      g_h);
    cudaGetSymbolAddress((void**)&ff,     g_ff);

    const float scale = 1.0f / sqrtf((float)DD);

    // batches z = h*B + b, HD = B: z/HD = head, z%HD = batch
    // 1) Q projection: [S,U] per (h,b)
    gemm(x, qw, q, nullptr, SS, UU, DD, HH * BB, BB,
         DD, UU, UU, 1,
         0, SS * DD,
         DD * UU, 0,
         BB * SS * UU, SS * UU,
         1.f, 0);

    // 2) K projection stored transposed: kT[h,b][u,s]
    gemm(x, kw, kT, nullptr, SS, UU, DD, HH * BB, BB,
         DD, UU, 1, SS,
         0, SS * DD,
         DD * UU, 0,
         BB * UU * SS, UU * SS,
         1.f, 0);

    // 3) V projection: [S,D] per (h,b)
    gemm(x, vw, v, nullptr, SS, DD, DD, HH * BB, BB,
         DD, DD, DD, 1,
         0, SS * DD,
         DD * DD, 0,
         BB * SS * DD, SS * DD,
         1.f, 0);

    // 4) scores = scale * Q @ K^T : [S,S] per (h,b)
    gemm(q, kT, scores, nullptr, SS, SS, UU, HH * BB, BB,
         UU, SS, SS, 1,
         BB * SS * UU, SS * UU,
         BB * UU * SS, UU * SS,
         BB * SS * SS, SS * SS,
         scale, 0);

    // 5) softmax rows
    softmax_k<<<HH * BB * SS, 256>>>(scores);

    // 6) attn = probs @ V, written straight into concat layout [B,S,H*D]
    gemm(scores, v, concat, nullptr, SS, DD, SS, HH * BB, BB,
         SS, DD, HH * DD, 1,
         BB * SS * SS, SS * SS,
         BB * SS * DD, SS * DD,
         DD, SS * HH * DD,
         1.f, 0);

    // 7) output projection: [B*S, 4096] @ [4096, 512]
    gemm(concat, lw, tmp, nullptr, BB * SS, DD, HH * DD, 1, 1,
         HH * DD, DD, DD, 1,
         0, 0, 0, 0, 0, 0,
         1.f, 0);

    // 8) h = LN(x + mha)
    ln_k<<<BB * SS, 256>>>(h, x, tmp, gamma1, beta1);

    // 9) ff = relu(h @ w1 + b1)
    gemm(h, w1, ff, b1, BB * SS, FF, DD, 1, 1,
         DD, FF, FF, 1,
         0, 0, 0, 0, 0, 0,
         1.f, 1);

    // 10) tmp = ff @ w2 + b2
    gemm(ff, w2, tmp, b2, BB * SS, DD, FF, 1, 1,
         FF, DD, DD, 1,
         0, 0, 0, 0, 0, 0,
         1.f, 0);

    // 11) out = LN(h + tmp)
    ln_k<<<BB * SS, 256>>>(out, h, tmp, gamma2, beta2);
}

// round 4
// speedup vs baseline: 1.0003x; 1.0003x over previous
#include <cuda_runtime.h>
#include <cuda_bf16.h>
#include <math.h>
#include <stdint.h>

// Problem constants
#define BB 8
#define SS 1024
#define DD 512
#define HH 8
#define UU 64
#define FF 2048
#define LN_EPS 1e-3f
#define SCALE 0.04419417382415922f   // 1/sqrt(512)

// ---------------- scratch (device globals; no allocation allowed) ----------
__device__ float g_q[HH * BB * SS * UU];            // [H,B,S,U]
__device__ float g_kT[HH * BB * UU * SS];           // [H,B,U,S]
__device__ float g_v[HH * BB * SS * DD];            // [H,B,S,D]
__device__ float g_m[HH * BB * SS];                 // row max
__device__ float g_l[HH * BB * SS];                 // row sum
__device__ float g_concat[BB * SS * (HH * DD)];     // [B,S,H*D]
__device__ float g_tmp[BB * SS * DD];               // mha out, then ff2 out
__device__ float g_h[BB * SS * DD];                 // LN1 output
__device__ float g_ff[BB * SS * FF];                // relu(ff1)

// ---------------- mma helpers ------------------------------------------------
__device__ __forceinline__ uint32_t f2tf32(float x) {
    uint32_t y;
    asm("cvt.rna.tf32.f32 %0, %1;" : "=r"(y) : "f"(x));
    return y;
}

__device__ __forceinline__ void mma_tf32(float* c, const uint32_t* a, const uint32_t* b) {
    asm volatile(
        "mma.sync.aligned.m16n8k8.row.col.f32.tf32.tf32.f32 "
        "{%0,%1,%2,%3}, {%4,%5,%6,%7}, {%8,%9}, {%0,%1,%2,%3};\n"
        : "+f"(c[0]), "+f"(c[1]), "+f"(c[2]), "+f"(c[3])
        : "r"(a[0]), "r"(a[1]), "r"(a[2]), "r"(a[3]), "r"(b[0]), "r"(b[1]));
}

// ---------------- tf32 tensor-core batched strided GEMM (round-2 engine) ----
#define BM 128
#define BN 128
#define BK 16
#define BKP 20

__global__ __launch_bounds__(128)
void gemm_tc(const float* __restrict__ A, const float* __restrict__ B,
             float* __restrict__ C, const float* __restrict__ bias,
             int M, int N, int K,
             int sAm, int sBk, int sCm, int sCn,
             int HD, int sA1, int sA2, int sB1, int sB2, int sC1, int sC2,
             float alpha, int relu)
{
    const int z = blockIdx.z;
    A += (size_t)(z / HD) * sA1 + (size_t)(z % HD) * sA2;
    B += (size_t)(z / HD) * sB1 + (size_t)(z % HD) * sB2;
    C += (size_t)(z / HD) * sC1 + (size_t)(z % HD) * sC2;

    const int row0 = blockIdx.y * BM;
    const int col0 = blockIdx.x * BN;
    const int tid  = threadIdx.x;
    const int w    = tid >> 5;
    const int lane = tid & 31;
    const int wm   = w & 1;
    const int wn   = w >> 1;
    const int r    = lane >> 2;
    const int cq   = lane & 3;

    __shared__ uint32_t As[2][BM][BKP];
    __shared__ uint32_t Bs[2][BN][BKP];

    float acc[4][8][4];
#pragma unroll
    for (int i = 0; i < 4; i++)
#pragma unroll
        for (int j = 0; j < 8; j++)
#pragma unroll
            for (int q = 0; q < 4; q++) acc[i][j][q] = 0.f;

    float rA[16], rB[16];
    const int la = tid >> 4;
    const int lb = tid & 15;

#pragma unroll
    for (int l = 0; l < 16; l++)
        rA[l] = A[(size_t)(row0 + la + 8 * l) * sAm + lb];
    {
        const int gn = col0 + tid;
        const bool okn = (gn < N);
#pragma unroll
        for (int l = 0; l < 16; l++)
            rB[l] = okn ? B[(size_t)l * sBk + gn] : 0.f;
    }
#pragma unroll
    for (int l = 0; l < 16; l++) As[0][la + 8 * l][lb] = f2tf32(rA[l]);
#pragma unroll
    for (int l = 0; l < 16; l++) Bs[0][tid][l] = f2tf32(rB[l]);
    __syncthreads();

    int cur = 0;
    for (int k0 = 0; k0 < K; k0 += BK) {
        const bool nxt = (k0 + BK) < K;
        if (nxt) {
            const int kn = k0 + BK;
#pragma unroll
            for (int l = 0; l < 16; l++)
                rA[l] = A[(size_t)(row0 + la + 8 * l) * sAm + (kn + lb)];
            const int gn = col0 + tid;
            const bool okn = (gn < N);
#pragma unroll
            for (int l = 0; l < 16; l++)
                rB[l] = okn ? B[(size_t)(kn + l) * sBk + gn] : 0.f;
        }

#pragma unroll
        for (int k8 = 0; k8 < BK; k8 += 8) {
            uint32_t af[4][4];
            uint32_t bf[8][2];
#pragma unroll
            for (int mt = 0; mt < 4; mt++) {
                const int row = wm * 64 + mt * 16 + r;
                af[mt][0] = As[cur][row][k8 + cq];
                af[mt][1] = As[cur][row + 8][k8 + cq];
                af[mt][2] = As[cur][row][k8 + cq + 4];
                af[mt][3] = As[cur][row + 8][k8 + cq + 4];
            }
#pragma unroll
            for (int nt = 0; nt < 8; nt++) {
                const int col = wn * 64 + nt * 8 + r;
                bf[nt][0] = Bs[cur][col][k8 + cq];
                bf[nt][1] = Bs[cur][col][k8 + cq + 4];
            }
#pragma unroll
            for (int mt = 0; mt < 4; mt++)
#pragma unroll
                for (int nt = 0; nt < 8; nt++)
                    mma_tf32(acc[mt][nt], af[mt], bf[nt]);
        }

        if (nxt) {
            const int nb = cur ^ 1;
#pragma unroll
            for (int l = 0; l < 16; l++) As[nb][la + 8 * l][lb] = f2tf32(rA[l]);
#pragma unroll
            for (int l = 0; l < 16; l++) Bs[nb][tid][l] = f2tf32(rB[l]);
            cur = nb;
            __syncthreads();
        }
    }

#pragma unroll
    for (int mt = 0; mt < 4; mt++) {
        const int rr0 = row0 + wm * 64 + mt * 16 + r;
        const int rr1 = rr0 + 8;
#pragma unroll
        for (int nt = 0; nt < 8; nt++) {
            const int cc0 = col0 + wn * 64 + nt * 8 + 2 * cq;
            const int cc1 = cc0 + 1;
            if (cc0 < N) {
                float v0 = acc[mt][nt][0] * alpha;
                float v2 = acc[mt][nt][2] * alpha;
                if (bias) { v0 += bias[cc0]; v2 += bias[cc0]; }
                if (relu) { v0 = fmaxf(v0, 0.f); v2 = fmaxf(v2, 0.f); }
                C[(size_t)rr0 * sCm + (size_t)cc0 * sCn] = v0;
                C[(size_t)rr1 * sCm + (size_t)cc0 * sCn] = v2;
            }
            if (cc1 < N) {
                float v1 = acc[mt][nt][1] * alpha;
                float v3 = acc[mt][nt][3] * alpha;
                if (bias) { v1 += bias[cc1]; v3 += bias[cc1]; }
                if (relu) { v1 = fmaxf(v1, 0.f); v3 = fmaxf(v3, 0.f); }
                C[(size_t)rr0 * sCm + (size_t)cc1 * sCn] = v1;
                C[(size_t)rr1 * sCm + (size_t)cc1 * sCn] = v3;
            }
        }
    }
}

// ---------------- pass 1: attention row stats (m, l) -------------------------
// grid (8, 64), block 256. dynamic smem: Qs[128][68] + Ks[64][136] + red[512]
__global__ __launch_bounds__(256)
void attn_stats(const float* __restrict__ Q, const float* __restrict__ KT,
                float* __restrict__ Mo, float* __restrict__ Lo)
{
    extern __shared__ uint32_t sm1[];
    uint32_t (*Qs)[68]  = (uint32_t(*)[68])sm1;
    uint32_t (*Ks)[136] = (uint32_t(*)[136])(sm1 + 128 * 68);
    float* red = (float*)(sm1 + 128 * 68 + 64 * 136);

    const int z  = blockIdx.y;
    const int q0 = blockIdx.x * 128;
    const float* Qg = Q  + (size_t)z * SS * UU;
    const float* Kg = KT + (size_t)z * UU * SS;

    const int tid = threadIdx.x;
    const int w = tid >> 5, lane = tid & 31;
    const int wm = w & 1, wn = w >> 1;
    const int r = lane >> 2, cq = lane & 3;

    // load Q tile (128 x 64)
    {
        const int row = tid >> 1;
        const int c0  = (tid & 1) * 32;
        const float* src = Qg + (size_t)(q0 + row) * UU + c0;
#pragma unroll
        for (int i = 0; i < 8; i++) {
            float4 v = *(const float4*)(src + i * 4);
            Qs[row][c0 + i * 4 + 0] = f2tf32(v.x);
            Qs[row][c0 + i * 4 + 1] = f2tf32(v.y);
            Qs[row][c0 + i * 4 + 2] = f2tf32(v.z);
            Qs[row][c0 + i * 4 + 3] = f2tf32(v.w);
        }
    }

    float m_run[8], l_run[8];
#pragma unroll
    for (int i = 0; i < 8; i++) { m_run[i] = -INFINITY; l_run[i] = 0.f; }

    for (int kt = 0; kt < 8; kt++) {
        const int t0 = kt * 128;
        // load KT tile (64 x 128)
        {
            const int u  = tid >> 2;
            const int c0 = (tid & 3) * 32;
            const float* src = Kg + (size_t)u * SS + t0 + c0;
#pragma unroll
            for (int i = 0; i < 8; i++) {
                float4 v = *(const float4*)(src + i * 4);
                Ks[u][c0 + i * 4 + 0] = f2tf32(v.x);
                Ks[u][c0 + i * 4 + 1] = f2tf32(v.y);
                Ks[u][c0 + i * 4 + 2] = f2tf32(v.z);
                Ks[u][c0 + i * 4 + 3] = f2tf32(v.w);
            }
        }
        __syncthreads();   // (A) tiles ready; also protects red reuse

        float acc[4][4][4];
#pragma unroll
        for (int i = 0; i < 4; i++)
#pragma unroll
            for (int j = 0; j < 4; j++)
#pragma unroll
                for (int q = 0; q < 4; q++) acc[i][j][q] = 0.f;

#pragma unroll
        for (int k8 = 0; k8 < 64; k8 += 8) {
            uint32_t af[4][4], bf[4][2];
#pragma unroll
            for (int mt = 0; mt < 4; mt++) {
                const int row = wm * 64 + mt * 16 + r;
                af[mt][0] = Qs[row][k8 + cq];
                af[mt][1] = Qs[row + 8][k8 + cq];
                af[mt][2] = Qs[row][k8 + cq + 4];
                af[mt][3] = Qs[row + 8][k8 + cq + 4];
            }
#pragma unroll
            for (int nt = 0; nt < 4; nt++) {
                const int col = wn * 32 + nt * 8 + r;
                bf[nt][0] = Ks[k8 + cq][col];
                bf[nt][1] = Ks[k8 + cq + 4][col];
            }
#pragma unroll
            for (int mt = 0; mt < 4; mt++)
#pragma unroll
                for (int nt = 0; nt < 4; nt++)
                    mma_tf32(acc[mt][nt], af[mt], bf[nt]);
        }

        // per-thread row maxima (scaled)
        float rm[8];
#pragma unroll
        for (int mt = 0; mt < 4; mt++) {
            float a0 = -INFINITY, a1 = -INFINITY;
#pragma unroll
            for (int nt = 0; nt < 4; nt++) {
                a0 = fmaxf(a0, fmaxf(acc[mt][nt][0], acc[mt][nt][1]));
                a1 = fmaxf(a1, fmaxf(acc[mt][nt][2], acc[mt][nt][3]));
            }
            rm[mt * 2]     = a0 * SCALE;
            rm[mt * 2 + 1] = a1 * SCALE;
        }
#pragma unroll
        for (int i = 0; i < 8; i++) {
            rm[i] = fmaxf(rm[i], __shfl_xor_sync(0xffffffffu, rm[i], 1));
            rm[i] = fmaxf(rm[i], __shfl_xor_sync(0xffffffffu, rm[i], 2));
        }
        if (cq == 0) {
#pragma unroll
            for (int mt = 0; mt < 4; mt++) {
                red[(wm * 64 + mt * 16 + r) * 4 + wn]     = rm[mt * 2];
                red[(wm * 64 + mt * 16 + r + 8) * 4 + wn] = rm[mt * 2 + 1];
            }
        }
        __syncthreads();   // (B)
        float m_new[8];
#pragma unroll
        for (int mt = 0; mt < 4; mt++) {
#pragma unroll
            for (int hh = 0; hh < 2; hh++) {
                const int row = wm * 64 + mt * 16 + r + hh * 8;
                float t = fmaxf(fmaxf(red[row * 4 + 0], red[row * 4 + 1]),
                                fmaxf(red[row * 4 + 2], red[row * 4 + 3]));
                m_new[mt * 2 + hh] = fmaxf(m_run[mt * 2 + hh], t);
            }
        }
        // per-thread row sums
        float sm_[8];
#pragma unroll
        for (int i = 0; i < 8; i++) sm_[i] = 0.f;
#pragma unroll
        for (int mt = 0; mt < 4; mt++)
#pragma unroll
            for (int nt = 0; nt < 4; nt++) {
                sm_[mt * 2]     += __expf(acc[mt][nt][0] * SCALE - m_new[mt * 2]);
                sm_[mt * 2]     += __expf(acc[mt][nt][1] * SCALE - m_new[mt * 2]);
                sm_[mt * 2 + 1] += __expf(acc[mt][nt][2] * SCALE - m_new[mt * 2 + 1]);
                sm_[mt * 2 + 1] += __expf(acc[mt][nt][3] * SCALE - m_new[mt * 2 + 1]);
            }
#pragma unroll
        for (int i = 0; i < 8; i++) {
            sm_[i] += __shfl_xor_sync(0xffffffffu, sm_[i], 1);
            sm_[i] += __shfl_xor_sync(0xffffffffu, sm_[i], 2);
        }
        __syncthreads();   // (C) max reads done before sum writes
        if (cq == 0) {
#pragma unroll
            for (int mt = 0; mt < 4; mt++) {
                red[(wm * 64 + mt * 16 + r) * 4 + wn]     = sm_[mt * 2];
                red[(wm * 64 + mt * 16 + r + 8) * 4 + wn] = sm_[mt * 2 + 1];
            }
        }
        __syncthreads();   // (D)
#pragma unroll
        for (int mt = 0; mt < 4; mt++)
#pragma unroll
            for (int hh = 0; hh < 2; hh++) {
                const int i = mt * 2 + hh;
                const int row = wm * 64 + mt * 16 + r + hh * 8;
                float tot = red[row * 4 + 0] + red[row * 4 + 1] +
                            red[row * 4 + 2] + red[row * 4 + 3];
                l_run[i] = l_run[i] * __expf(m_run[i] - m_new[i]) + tot;
                m_run[i] = m_new[i];
            }
    }

    if (wn == 0 && cq == 0) {
#pragma unroll
        for (int mt = 0; mt < 4; mt++)
#pragma unroll
            for (int hh = 0; hh < 2; hh++) {
                const int row = wm * 64 + mt * 16 + r + hh * 8;
                const size_t idx = (size_t)z * SS + q0 + row;
                Mo[idx] = m_run[mt * 2 + hh];
                Lo[idx] = l_run[mt * 2 + hh];
            }
    }
}

// ---------------- pass 2: fused P@V with score recompute ---------------------
// grid (4, 8, 64), block 256.
// dynamic smem: Qs[128][68] + Ks[64][72] + Ps[128][68] + Vs[64][136]
__global__ __launch_bounds__(256)
void attn_out(const float* __restrict__ Q, const float* __restrict__ KT,
              const float* __restrict__ V, const float* __restrict__ Mi,
              const float* __restrict__ Li, float* __restrict__ Out)
{
    extern __shared__ uint32_t sm2[];
    uint32_t (*Qs)[68]  = (uint32_t(*)[68])sm2;
    uint32_t (*Ks)[72]  = (uint32_t(*)[72])(sm2 + 128 * 68);
    uint32_t (*Ps)[68]  = (uint32_t(*)[68])(sm2 + 128 * 68 + 64 * 72);
    uint32_t (*Vs)[136] = (uint32_t(*)[136])(sm2 + 128 * 68 + 64 * 72 + 128 * 68);

    const int z  = blockIdx.z;
    const int q0 = blockIdx.y * 128;
    const int d0 = blockIdx.x * 128;
    const int hh_ = z >> 3;
    const int bb_ = z & 7;
    const float* Qg = Q  + (size_t)z * SS * UU;
    const float* Kg = KT + (size_t)z * UU * SS;
    const float* Vg = V  + (size_t)z * SS * DD;

    const int tid = threadIdx.x;
    const int w = tid >> 5, lane = tid & 31;
    const int wm = w & 1, wn = w >> 1;
    const int r = lane >> 2, cq = lane & 3;

    // load Q tile
    {
        const int row = tid >> 1;
        const int c0  = (tid & 1) * 32;
        const float* src = Qg + (size_t)(q0 + row) * UU + c0;
#pragma unroll
        for (int i = 0; i < 8; i++) {
            float4 v = *(const float4*)(src + i * 4);
            Qs[row][c0 + i * 4 + 0] = f2tf32(v.x);
            Qs[row][c0 + i * 4 + 1] = f2tf32(v.y);
            Qs[row][c0 + i * 4 + 2] = f2tf32(v.z);
            Qs[row][c0 + i * 4 + 3] = f2tf32(v.w);
        }
    }

    // per-thread row stats
    float m8[8], li8[8];
#pragma unroll
    for (int mt = 0; mt < 4; mt++)
#pragma unroll
        for (int hh = 0; hh < 2; hh++) {
            const int row = wm * 64 + mt * 16 + r + hh * 8;
            const size_t idx = (size_t)z * SS + q0 + row;
            m8[mt * 2 + hh]  = Mi[idx];
            li8[mt * 2 + hh] = 1.f / Li[idx];
        }

    float acco[4][4][4];
#pragma unroll
    for (int i = 0; i < 4; i++)
#pragma unroll
        for (int j = 0; j < 4; j++)
#pragma unroll
            for (int q = 0; q < 4; q++) acco[i][j][q] = 0.f;

    for (int kt = 0; kt < 16; kt++) {
        const int t0 = kt * 64;
        // KT tile (64 x 64)
        {
            const int u  = tid >> 2;
            const int c0 = (tid & 3) * 16;
            const float* src = Kg + (size_t)u * SS + t0 + c0;
#pragma unroll
            for (int i = 0; i < 4; i++) {
                float4 v = *(const float4*)(src + i * 4);
                Ks[u][c0 + i * 4 + 0] = f2tf32(v.x);
                Ks[u][c0 + i * 4 + 1] = f2tf32(v.y);
                Ks[u][c0 + i * 4 + 2] = f2tf32(v.z);
                Ks[u][c0 + i * 4 + 3] = f2tf32(v.w);
            }
        }
        // V tile (64 x 128)
        {
            const int k  = tid >> 2;
            const int c0 = (tid & 3) * 32;
            const float* src = Vg + (size_t)(t0 + k) * DD + d0 + c0;
#pragma unroll
            for (int i = 0; i < 8; i++) {
                float4 v = *(const float4*)(src + i * 4);
                Vs[k][c0 + i * 4 + 0] = f2tf32(v.x);
                Vs[k][c0 + i * 4 + 1] = f2tf32(v.y);
                Vs[k][c0 + i * 4 + 2] = f2tf32(v.z);
                Vs[k][c0 + i * 4 + 3] = f2tf32(v.w);
            }
        }
        __syncthreads();

        // S = Q @ KT-tile  (128 x 64, k=64)
        float accs[4][2][4];
#pragma unroll
        for (int i = 0; i < 4; i++)
#pragma unroll
            for (int j = 0; j < 2; j++)
#pragma unroll
                for (int q = 0; q < 4; q++) accs[i][j][q] = 0.f;
#pragma unroll
        for (int k8 = 0; k8 < 64; k8 += 8) {
            uint32_t af[4][4], bf[2][2];
#pragma unroll
            for (int mt = 0; mt < 4; mt++) {
                const int row = wm * 64 + mt * 16 + r;
                af[mt][0] = Qs[row][k8 + cq];
                af[mt][1] = Qs[row + 8][k8 + cq];
                af[mt][2] = Qs[row][k8 + cq + 4];
                af[mt][3] = Qs[row + 8][k8 + cq + 4];
            }
#pragma unroll
            for (int nt = 0; nt < 2; nt++) {
                const int col = wn * 16 + nt * 8 + r;
                bf[nt][0] = Ks[k8 + cq][col];
                bf[nt][1] = Ks[k8 + cq + 4][col];
            }
#pragma unroll
            for (int mt = 0; mt < 4; mt++)
#pragma unroll
                for (int nt = 0; nt < 2; nt++)
                    mma_tf32(accs[mt][nt], af[mt], bf[nt]);
        }

        // P = exp(S*scale - m) / l  -> smem (tf32)
#pragma unroll
        for (int mt = 0; mt < 4; mt++)
#pragma unroll
            for (int nt = 0; nt < 2; nt++)
#pragma unroll
                for (int q = 0; q < 4; q++) {
                    const int i   = mt * 2 + (q >> 1);
                    const int row = wm * 64 + mt * 16 + r + (q >> 1) * 8;
                    const int col = wn * 16 + nt * 8 + 2 * cq + (q & 1);
                    float p = __expf(accs[mt][nt][q] * SCALE - m8[i]) * li8[i];
                    Ps[row][col] = f2tf32(p);
                }
        __syncthreads();

        // O += P @ V-tile  (128 x 128, k=64)
#pragma unroll
        for (int k8 = 0; k8 < 64; k8 += 8) {
            uint32_t af[4][4], bf[4][2];
#pragma unroll
            for (int mt = 0; mt < 4; mt++) {
                const int row = wm * 64 + mt * 16 + r;
                af[mt][0] = Ps[row][k8 + cq];
                af[mt][1] = Ps[row + 8][k8 + cq];
                af[mt][2] = Ps[row][k8 + cq + 4];
                af[mt][3] = Ps[row + 8][k8 + cq + 4];
            }
#pragma unroll
            for (int nt = 0; nt < 4; nt++) {
                const int col = wn * 32 + nt * 8 + r;
                bf[nt][0] = Vs[k8 + cq][col];
                bf[nt][1] = Vs[k8 + cq + 4][col];
            }
#pragma unroll
            for (int mt = 0; mt < 4; mt++)
#pragma unroll
                for (int nt = 0; nt < 4; nt++)
                    mma_tf32(acco[mt][nt], af[mt], bf[nt]);
        }
        __syncthreads();
    }

    // epilogue -> concat [B,S,H*D]
    float* Ob = Out + ((size_t)bb_ * SS + q0) * (HH * DD) + hh_ * DD + d0;
#pragma unroll
    for (int mt = 0; mt < 4; mt++) {
        const int rr0 = wm * 64 + mt * 16 + r;
        const int rr1 = rr0 + 8;
#pragma unroll
        for (int nt = 0; nt < 4; nt++) {
            const int cc = wn * 32 + nt * 8 + 2 * cq;
            Ob[(size_t)rr0 * (HH * DD) + cc]     = acco[mt][nt][0];
            Ob[(size_t)rr0 * (HH * DD) + cc + 1] = acco[mt][nt][1];
            Ob[(size_t)rr1 * (HH * DD) + cc]     = acco[mt][nt][2];
            Ob[(size_t)rr1 * (HH * DD) + cc + 1] = acco[mt][nt][3];
        }
    }
}

// ---------------- residual + layernorm (rows of 512) ------------------------
__global__ __launch_bounds__(256)
void ln_k(float* __restrict__ out, const float* __restrict__ a,
          const float* __restrict__ b, const float* __restrict__ gamma,
          const float* __restrict__ beta)
{
    size_t base = (size_t)blockIdx.x * DD;
    int t = threadIdx.x;
    float x0 = a[base + t]       + b[base + t];
    float x1 = a[base + t + 256] + b[base + t + 256];

    __shared__ float r1[256], r2[256];
    r1[t] = x0 + x1;
    r2[t] = x0 * x0 + x1 * x1;
    __syncthreads();
    for (int s = 128; s > 0; s >>= 1) {
        if (t < s) { r1[t] += r1[t + s]; r2[t] += r2[t + s]; }
        __syncthreads();
    }
    float mean = r1[0] * (1.f / DD);
    float var  = r2[0] * (1.f / DD) - mean * mean;
    float rstd = rsqrtf(var + LN_EPS);

    out[base + t]       = gamma[t]       * (x0 - mean) * rstd + beta[t];
    out[base + t + 256] = gamma[t + 256] * (x1 - mean) * rstd + beta[t + 256];
}

// ---------------- host side --------------------------------------------------
static void gemm(const float* A, const float* B, float* C, const float* bias,
                 int M, int N, int K, int nb, int HD,
                 int sAm, int sBk, int sCm, int sCn,
                 int sA1, int sA2, int sB1, int sB2, int sC1, int sC2,
                 float alpha, int relu)
{
    dim3 grid((N + BN - 1) / BN, (M + BM - 1) / BM, nb);
    gemm_tc<<<grid, 128>>>(A, B, C, bias, M, N, K,
                           sAm, sBk, sCm, sCn,
                           HD, sA1, sA2, sB1, sB2, sC1, sC2, alpha, relu);
}

#define SMEM_STATS ((128 * 68 + 64 * 136) * 4 + 512 * 4)
#define SMEM_OUT   ((128 * 68 + 64 * 72 + 128 * 68 + 64 * 136) * 4)

extern "C" void kernel_launch(void* const* d_in, const int* in_sizes, int n_in,
                              void* d_out, int out_size)
{
    const float* x      = (const float*)d_in[0];
    const float* qw     = (const float*)d_in[1];
    const float* kw     = (const float*)d_in[2];
    const float* vw     = (const float*)d_in[3];
    const float* lw     = (const float*)d_in[4];
    const float* gamma1 = (const float*)d_in[5];
    const float* beta1  = (const float*)d_in[6];
    const float* w1     = (const float*)d_in[7];
    const float* b1     = (const float*)d_in[8];
    const float* w2     = (const float*)d_in[9];
    const float* b2     = (const float*)d_in[10];
    const float* gamma2 = (const float*)d_in[11];
    const float* beta2  = (const float*)d_in[12];
    float* out = (float*)d_out;

    float *q, *kT, *v, *mbuf, *lbuf, *concat, *tmp, *h, *ff;
    cudaGetSymbolAddress((void**)&q,      g_q);
    cudaGetSymbolAddress((void**)&kT,     g_kT);
    cudaGetSymbolAddress((void**)&v,      g_v);
    cudaGetSymbolAddress((void**)&mbuf,   g_m);
    cudaGetSymbolAddress((void**)&lbuf,   g_l);
    cudaGetSymbolAddress((void**)&concat, g_concat);
    cudaGetSymbolAddress((void**)&tmp,    g_tmp);
    cudaGetSymbolAddress((void**)&h,      g_h);
    cudaGetSymbolAddress((void**)&ff,     g_ff);

    cudaFuncSetAttribute(attn_stats, cudaFuncAttributeMaxDynamicSharedMemorySize, SMEM_STATS);
    cudaFuncSetAttribute(attn_out,   cudaFuncAttributeMaxDynamicSharedMemorySize, SMEM_OUT);

    // 1) Q projection: [S,U] per (h,b)
    gemm(x, qw, q, nullptr, SS, UU, DD, HH * BB, BB,
         DD, UU, UU, 1,
         0, SS * DD,
         DD * UU, 0,
         BB * SS * UU, SS * UU,
         1.f, 0);

    // 2) K projection stored transposed: kT[h,b][u,s]
    gemm(x, kw, kT, nullptr, SS, UU, DD, HH * BB, BB,
         DD, UU, 1, SS,
         0, SS * DD,
         DD * UU, 0,
         BB * UU * SS, UU * SS,
         1.f, 0);

    // 3) V projection: [S,D] per (h,b)
    gemm(x, vw, v, nullptr, SS, DD, DD, HH * BB, BB,
         DD, DD, DD, 1,
         0, SS * DD,
         DD * DD, 0,
         BB * SS * DD, SS * DD,
         1.f, 0);

    // 4) attention row stats (m, l)
    attn_stats<<<dim3(8, 64), 256, SMEM_STATS>>>(q, kT, mbuf, lbuf);

    // 5) fused softmax + P@V -> concat layout [B,S,H*D]
    attn_out<<<dim3(4, 8, 64), 256, SMEM_OUT>>>(q, kT, v, mbuf, lbuf, concat);

    // 6) output projection: [B*S, 4096] @ [4096, 512]
    gemm(concat, lw, tmp, nullptr, BB * SS, DD, HH * DD, 1, 1,
         HH * DD, DD, DD, 1,
         0, 0, 0, 0, 0, 0,
         1.f, 0);

    // 7) h = LN(x + mha)
    ln_k<<<BB * SS, 256>>>(h, x, tmp, gamma1, beta1);

    // 8) ff = relu(h @ w1 + b1)
    gemm(h, w1, ff, b1, BB * SS, FF, DD, 1, 1,
         DD, FF, FF, 1,
         0, 0, 0, 0, 0, 0,
         1.f, 1);

    // 9) tmp = ff @ w2 + b2
    gemm(ff, w2, tmp, b2, BB * SS, DD, FF, 1, 1,
         FF, DD, DD, 1,
         0, 0, 0, 0, 0, 0,
         1.f, 0);

    // 10) out = LN(h + tmp)
    ln_k<<<BB * SS, 256>>>(out, h, tmp, gamma2, beta2);
}

// round 5
// speedup vs baseline: 1.0205x; 1.0203x over previous
#include <cuda_runtime.h>
#include <cuda_bf16.h>
#include <math.h>
#include <stdint.h>

// Problem constants
#define BB 8
#define SS 1024
#define DD 512
#define HH 8
#define UU 64
#define FF 2048
#define LN_EPS 1e-3f

// ---------------- scratch (device globals; no allocation allowed) ----------
__device__ float g_q[HH * BB * SS * UU];            // [H,B,S,U]
__device__ float g_kT[HH * BB * UU * SS];           // [H,B,U,S]
__device__ float g_v[HH * BB * SS * DD];            // [H,B,S,D]
__device__ float g_scores[(size_t)HH * BB * SS * SS];  // [H,B,S,S]
__device__ float g_concat[BB * SS * (HH * DD)];     // [B,S,H*D]
__device__ float g_tmp[BB * SS * DD];               // mha out, then ff2 out
__device__ float g_h[BB * SS * DD];                 // LN1 output
__device__ float g_ff[BB * SS * FF];                // relu(ff1)

// ---------------- helpers ---------------------------------------------------
__device__ __forceinline__ void mma_tf32(float* c, const uint32_t* a, const uint32_t* b) {
    asm volatile(
        "mma.sync.aligned.m16n8k8.row.col.f32.tf32.tf32.f32 "
        "{%0,%1,%2,%3}, {%4,%5,%6,%7}, {%8,%9}, {%0,%1,%2,%3};\n"
        : "+f"(c[0]), "+f"(c[1]), "+f"(c[2]), "+f"(c[3])
        : "r"(a[0]), "r"(a[1]), "r"(a[2]), "r"(a[3]), "r"(b[0]), "r"(b[1]));
}

__device__ __forceinline__ void cp_async16(void* smem_dst, const void* gmem_src, int src_bytes) {
    uint32_t s = (uint32_t)__cvta_generic_to_shared(smem_dst);
    asm volatile("cp.async.cg.shared.global [%0], [%1], 16, %2;\n"
                 :: "r"(s), "l"(gmem_src), "r"(src_bytes));
}
__device__ __forceinline__ void cp_commit() {
    asm volatile("cp.async.commit_group;\n");
}
template <int Nn>
__device__ __forceinline__ void cp_wait() {
    asm volatile("cp.async.wait_group %0;\n" :: "n"(Nn));
}

// ---------------- tf32 tensor-core batched strided GEMM ---------------------
// C[z][m,n] = alpha * sum_k A[z][m,k]*B[z][k,n] (+bias[n]) (+relu)
// Assumes: A k-contiguous, B n-contiguous, M % 128 == 0, K % 32 == 0,
//          sAm % 4 == 0, sBk % 4 == 0, N % 4 == 0 (N guarded).
#define BM 128
#define BN 128
#define BK 32
#define AKP 36    // A smem k-stride (floats): 16B-aligned rows, frag banks 4r+cq
#define BNP 136   // B smem n-stride (floats): 16B-aligned rows, frag banks 8cq+r
#define STAGES 3
#define GEMM_SMEM ((STAGES * (BM * AKP + BK * BNP)) * 4)

__global__ __launch_bounds__(128)
void gemm_tc(const float* __restrict__ A, const float* __restrict__ B,
             float* __restrict__ C, const float* __restrict__ bias,
             int M, int N, int K,
             int sAm, int sBk, int sCm, int sCn,
             int HD, int sA1, int sA2, int sB1, int sB2, int sC1, int sC2,
             float alpha, int relu)
{
    extern __shared__ float smx[];
    float* sA = smx;                               // [STAGES][BM][AKP]
    float* sB = smx + STAGES * BM * AKP;           // [STAGES][BK][BNP]

    const int z = blockIdx.z;
    A += (size_t)(z / HD) * sA1 + (size_t)(z % HD) * sA2;
    B += (size_t)(z / HD) * sB1 + (size_t)(z % HD) * sB2;
    C += (size_t)(z / HD) * sC1 + (size_t)(z % HD) * sC2;

    const int row0 = blockIdx.y * BM;
    const int col0 = blockIdx.x * BN;
    const int tid  = threadIdx.x;
    const int w    = tid >> 5;
    const int lane = tid & 31;
    const int wm   = w & 1;          // 2 warps over M (64 rows)
    const int wn   = w >> 1;         // 2 warps over N (64 cols)
    const int r    = lane >> 2;      // 0..7
    const int cq   = lane & 3;       // 0..3

    // loader geometry
    const float* a_src_base = A + (size_t)(row0 + tid) * sAm;      // 1 row/thread
    const int brow = tid >> 2;            // 0..31
    const int bcol = (tid & 3) * 32;      // 0,32,64,96
    const float* b_src_base = B + (size_t)brow * sBk + col0 + bcol;

    float acc[4][8][4];
#pragma unroll
    for (int i = 0; i < 4; i++)
#pragma unroll
        for (int j = 0; j < 8; j++)
#pragma unroll
            for (int q = 0; q < 4; q++) acc[i][j][q] = 0.f;

    const int ntiles = K / BK;

    // ---- prologue: issue loads for tiles 0..STAGES-2 ----
#pragma unroll
    for (int s = 0; s < STAGES - 1; s++) {
        if (s < ntiles) {
            const int kt = s * BK;
            float* aD = sA + s * BM * AKP + tid * AKP;
            const float* aS = a_src_base + kt;
#pragma unroll
            for (int c = 0; c < 8; c++)
                cp_async16(aD + c * 4, aS + c * 4, 16);
            float* bD = sB + s * BK * BNP + brow * BNP + bcol;
            const float* bS = b_src_base + (size_t)kt * sBk;
#pragma unroll
            for (int c = 0; c < 8; c++) {
                const bool ok = (col0 + bcol + c * 4) < N;
                cp_async16(bD + c * 4, ok ? (bS + c * 4) : (const float*)B, ok ? 16 : 0);
            }
        }
        cp_commit();
    }

    for (int t = 0; t < ntiles; t++) {
        cp_wait<STAGES - 2>();
        __syncthreads();

        // issue loads for tile t+STAGES-1 (overlaps with compute below)
        const int tl = t + STAGES - 1;
        if (tl < ntiles) {
            const int buf = tl % STAGES;
            const int kt  = tl * BK;
            float* aD = sA + buf * BM * AKP + tid * AKP;
            const float* aS = a_src_base + kt;
#pragma unroll
            for (int c = 0; c < 8; c++)
                cp_async16(aD + c * 4, aS + c * 4, 16);
            float* bD = sB + buf * BK * BNP + brow * BNP + bcol;
            const float* bS = b_src_base + (size_t)kt * sBk;
#pragma unroll
            for (int c = 0; c < 8; c++) {
                const bool ok = (col0 + bcol + c * 4) < N;
                cp_async16(bD + c * 4, ok ? (bS + c * 4) : (const float*)B, ok ? 16 : 0);
            }
        }
        cp_commit();

        // ---- compute on buffer t % STAGES ----
        const uint32_t* Au = (const uint32_t*)(sA + (t % STAGES) * BM * AKP);
        const uint32_t* Bu = (const uint32_t*)(sB + (t % STAGES) * BK * BNP);
#pragma unroll
        for (int k8 = 0; k8 < BK; k8 += 8) {
            uint32_t af[4][4];
            uint32_t bf[8][2];
#pragma unroll
            for (int mt = 0; mt < 4; mt++) {
                const int row = wm * 64 + mt * 16 + r;
                af[mt][0] = Au[(row)     * AKP + k8 + cq];
                af[mt][1] = Au[(row + 8) * AKP + k8 + cq];
                af[mt][2] = Au[(row)     * AKP + k8 + cq + 4];
                af[mt][3] = Au[(row + 8) * AKP + k8 + cq + 4];
            }
#pragma unroll
            for (int nt = 0; nt < 8; nt++) {
                const int col = wn * 64 + nt * 8 + r;
                bf[nt][0] = Bu[(k8 + cq)     * BNP + col];
                bf[nt][1] = Bu[(k8 + cq + 4) * BNP + col];
            }
#pragma unroll
            for (int mt = 0; mt < 4; mt++)
#pragma unroll
                for (int nt = 0; nt < 8; nt++)
                    mma_tf32(acc[mt][nt], af[mt], bf[nt]);
        }
    }

    // ---- epilogue ----
#pragma unroll
    for (int mt = 0; mt < 4; mt++) {
        const int rr0 = row0 + wm * 64 + mt * 16 + r;
        const int rr1 = rr0 + 8;
#pragma unroll
        for (int nt = 0; nt < 8; nt++) {
            const int cc0 = col0 + wn * 64 + nt * 8 + 2 * cq;
            const int cc1 = cc0 + 1;
            if (cc0 < N) {
                float v0 = acc[mt][nt][0] * alpha;
                float v2 = acc[mt][nt][2] * alpha;
                if (bias) { v0 += bias[cc0]; v2 += bias[cc0]; }
                if (relu) { v0 = fmaxf(v0, 0.f); v2 = fmaxf(v2, 0.f); }
                C[(size_t)rr0 * sCm + (size_t)cc0 * sCn] = v0;
                C[(size_t)rr1 * sCm + (size_t)cc0 * sCn] = v2;
            }
            if (cc1 < N) {
                float v1 = acc[mt][nt][1] * alpha;
                float v3 = acc[mt][nt][3] * alpha;
                if (bias) { v1 += bias[cc1]; v3 += bias[cc1]; }
                if (relu) { v1 = fmaxf(v1, 0.f); v3 = fmaxf(v3, 0.f); }
                C[(size_t)rr0 * sCm + (size_t)cc1 * sCn] = v1;
                C[(size_t)rr1 * sCm + (size_t)cc1 * sCn] = v3;
            }
        }
    }
}

// ---------------- softmax over rows of length 1024 --------------------------
__global__ __launch_bounds__(256)
void softmax_k(float* __restrict__ S)
{
    float4* p = (float4*)(S + (size_t)blockIdx.x * 1024);
    const int t = threadIdx.x;
    const int lane = t & 31, wid = t >> 5;
    __shared__ float red[8];

    float4 v = p[t];
    float m = fmaxf(fmaxf(v.x, v.y), fmaxf(v.z, v.w));
#pragma unroll
    for (int s = 16; s > 0; s >>= 1) m = fmaxf(m, __shfl_xor_sync(0xffffffffu, m, s));
    if (lane == 0) red[wid] = m;
    __syncthreads();
    m = red[lane & 7];
#pragma unroll
    for (int s = 4; s > 0; s >>= 1) m = fmaxf(m, __shfl_xor_sync(0xffffffffu, m, s));
    m = __shfl_sync(0xffffffffu, m, 0);

    v.x = __expf(v.x - m); v.y = __expf(v.y - m);
    v.z = __expf(v.z - m); v.w = __expf(v.w - m);
    float sum = v.x + v.y + v.z + v.w;
#pragma unroll
    for (int s = 16; s > 0; s >>= 1) sum += __shfl_xor_sync(0xffffffffu, sum, s);
    __syncthreads();
    if (lane == 0) red[wid] = sum;
    __syncthreads();
    sum = red[lane & 7];
#pragma unroll
    for (int s = 4; s > 0; s >>= 1) sum += __shfl_xor_sync(0xffffffffu, sum, s);
    sum = __shfl_sync(0xffffffffu, sum, 0);

    float inv = 1.f / sum;
    v.x *= inv; v.y *= inv; v.z *= inv; v.w *= inv;
    p[t] = v;
}

// ---------------- residual + layernorm (rows of 512) ------------------------
__global__ __launch_bounds__(256)
void ln_k(float* __restrict__ out, const float* __restrict__ a,
          const float* __restrict__ b, const float* __restrict__ gamma,
          const float* __restrict__ beta)
{
    size_t base = (size_t)blockIdx.x * DD;
    int t = threadIdx.x;
    float x0 = a[base + t]       + b[base + t];
    float x1 = a[base + t + 256] + b[base + t + 256];

    __shared__ float r1[256], r2[256];
    r1[t] = x0 + x1;
    r2[t] = x0 * x0 + x1 * x1;
    __syncthreads();
    for (int s = 128; s > 0; s >>= 1) {
        if (t < s) { r1[t] += r1[t + s]; r2[t] += r2[t + s]; }
        __syncthreads();
    }
    float mean = r1[0] * (1.f / DD);
    float var  = r2[0] * (1.f / DD) - mean * mean;
    float rstd = rsqrtf(var + LN_EPS);

    out[base + t]       = gamma[t]       * (x0 - mean) * rstd + beta[t];
    out[base + t + 256] = gamma[t + 256] * (x1 - mean) * rstd + beta[t + 256];
}

// ---------------- host side --------------------------------------------------
static void gemm(const float* A, const float* B, float* C, const float* bias,
                 int M, int N, int K, int nb, int HD,
                 int sAm, int sBk, int sCm, int sCn,
                 int sA1, int sA2, int sB1, int sB2, int sC1, int sC2,
                 float alpha, int relu)
{
    dim3 grid((N + BN - 1) / BN, (M + BM - 1) / BM, nb);
    gemm_tc<<<grid, 128, GEMM_SMEM>>>(A, B, C, bias, M, N, K,
                                      sAm, sBk, sCm, sCn,
                                      HD, sA1, sA2, sB1, sB2, sC1, sC2, alpha, relu);
}

extern "C" void kernel_launch(void* const* d_in, const int* in_sizes, int n_in,
                              void* d_out, int out_size)
{
    const float* x      = (const float*)d_in[0];
    const float* qw     = (const float*)d_in[1];
    const float* kw     = (const float*)d_in[2];
    const float* vw     = (const float*)d_in[3];
    const float* lw     = (const float*)d_in[4];
    const float* gamma1 = (const float*)d_in[5];
    const float* beta1  = (const float*)d_in[6];
    const float* w1     = (const float*)d_in[7];
    const float* b1     = (const float*)d_in[8];
    const float* w2     = (const float*)d_in[9];
    const float* b2     = (const float*)d_in[10];
    const float* gamma2 = (const float*)d_in[11];
    const float* beta2  = (const float*)d_in[12];
    float* out = (float*)d_out;

    float *q, *kT, *v, *scores, *concat, *tmp, *h, *ff;
    cudaGetSymbolAddress((void**)&q,      g_q);
    cudaGetSymbolAddress((void**)&kT,     g_kT);
    cudaGetSymbolAddress((void**)&v,      g_v);
    cudaGetSymbolAddress((void**)&scores, g_scores);
    cudaGetSymbolAddress((void**)&concat, g_concat);
    cudaGetSymbolAddress((void**)&tmp,    g_tmp);
    cudaGetSymbolAddress((void**)&h,      g_h);
    cudaGetSymbolAddress((void**)&ff,     g_ff);

    cudaFuncSetAttribute(gemm_tc, cudaFuncAttributeMaxDynamicSharedMemorySize, GEMM_SMEM);

    const float scale = 1.0f / sqrtf((float)DD);

    // batches z = h*B + b, HD = B: z/HD = head, z%HD = batch
    // 1) Q projection: [S,U] per (h,b)
    gemm(x, qw, q, nullptr, SS, UU, DD, HH * BB, BB,
         DD, UU, UU, 1,
         0, SS * DD,
         DD * UU, 0,
         BB * SS * UU, SS * UU,
         1.f, 0);

    // 2) K projection stored transposed: kT[h,b][u,s]
    gemm(x, kw, kT, nullptr, SS, UU, DD, HH * BB, BB,
         DD, UU, 1, SS,
         0, SS * DD,
         DD * UU, 0,
         BB * UU * SS, UU * SS,
         1.f, 0);

    // 3) V projection: [S,D] per (h,b)
    gemm(x, vw, v, nullptr, SS, DD, DD, HH * BB, BB,
         DD, DD, DD, 1,
         0, SS * DD,
         DD * DD, 0,
         BB * SS * DD, SS * DD,
         1.f, 0);

    // 4) scores = scale * Q @ K^T : [S,S] per (h,b)   (K=64 -> 2 k-tiles)
    gemm(q, kT, scores, nullptr, SS, SS, UU, HH * BB, BB,
         UU, SS, SS, 1,
         BB * SS * UU, SS * UU,
         BB * UU * SS, UU * SS,
         BB * SS * SS, SS * SS,
         scale, 0);

    // 5) softmax rows
    softmax_k<<<HH * BB * SS, 256>>>(scores);

    // 6) attn = probs @ V, written straight into concat layout [B,S,H*D]
    gemm(scores, v, concat, nullptr, SS, DD, SS, HH * BB, BB,
         SS, DD, HH * DD, 1,
         BB * SS * SS, SS * SS,
         BB * SS * DD, SS * DD,
         DD, SS * HH * DD,
         1.f, 0);

    // 7) output projection: [B*S, 4096] @ [4096, 512]
    gemm(concat, lw, tmp, nullptr, BB * SS, DD, HH * DD, 1, 1,
         HH * DD, DD, DD, 1,
         0, 0, 0, 0, 0, 0,
         1.f, 0);

    // 8) h = LN(x + mha)
    ln_k<<<BB * SS, 256>>>(h, x, tmp, gamma1, beta1);

    // 9) ff = relu(h @ w1 + b1)
    gemm(h, w1, ff, b1, BB * SS, FF, DD, 1, 1,
         DD, FF, FF, 1,
         0, 0, 0, 0, 0, 0,
         1.f, 1);

    // 10) tmp = ff @ w2 + b2
    gemm(ff, w2, tmp, b2, BB * SS, DD, FF, 1, 1,
         FF, DD, DD, 1,
         0, 0, 0, 0, 0, 0,
         1.f, 0);

    // 11) out = LN(h + tmp)
    ln_k<<<BB * SS, 256>>>(out, h, tmp, gamma2, beta2);
}

// round 9
// speedup vs baseline: 1.3000x; 1.2739x over previous
#include <cuda_runtime.h>
#include <cuda_bf16.h>
#include <math.h>
#include <stdint.h>

// Problem constants
#define BB 8
#define SS 1024
#define DD 512
#define HH 8
#define UU 64
#define FF 2048
#define LN_EPS 1e-3f

// ---------------- scratch (device globals; no allocation allowed) ----------
__device__ float g_q[HH * BB * SS * UU];            // [H,B,S,U]
__device__ float g_kT[HH * BB * UU * SS];           // [H,B,U,S]
__device__ float g_v[HH * BB * SS * DD];            // [H,B,S,D]
__device__ float g_scores[(size_t)HH * BB * SS * SS];  // [H,B,S,S]
__device__ float g_concat[BB * SS * (HH * DD)];     // [B,S,H*D]
__device__ float g_tmp[BB * SS * DD];               // mha out, then ff2 out
__device__ float g_h[BB * SS * DD];                 // LN1 output
__device__ float g_ff[BB * SS * FF];                // relu(ff1)

// ---------------- helpers ----------------------------------------------------
__device__ __forceinline__ uint32_t f2tf32(float x) {
    uint32_t y;
    asm("cvt.rna.tf32.f32 %0, %1;" : "=r"(y) : "f"(x));
    return y;
}

__device__ __forceinline__ void mma_tf32(float* c, const uint32_t* a, const uint32_t* b) {
    asm volatile(
        "mma.sync.aligned.m16n8k8.row.col.f32.tf32.tf32.f32 "
        "{%0,%1,%2,%3}, {%4,%5,%6,%7}, {%8,%9}, {%0,%1,%2,%3};\n"
        : "+f"(c[0]), "+f"(c[1]), "+f"(c[2]), "+f"(c[3])
        : "r"(a[0]), "r"(a[1]), "r"(a[2]), "r"(a[3]), "r"(b[0]), "r"(b[1]));
}

__device__ __forceinline__ void ldsm4(uint32_t& r0, uint32_t& r1, uint32_t& r2, uint32_t& r3,
                                      uint32_t addr) {
    asm volatile("ldmatrix.sync.aligned.m8n8.x4.shared.b16 {%0,%1,%2,%3}, [%4];"
                 : "=r"(r0), "=r"(r1), "=r"(r2), "=r"(r3) : "r"(addr));
}

__device__ __forceinline__ uint32_t smem_u32(const void* p) {
    uint32_t a;
    asm("{ .reg .u64 t; cvta.to.shared.u64 t, %1; cvt.u32.u64 %0, t; }" : "=r"(a) : "l"(p));
    return a;
}

// ---------------- tf32 tensor-core batched strided GEMM ---------------------
// C[z][m,n] = alpha * sum_k A[z][m,k]*B[z][k,n] (+bias[n]) (+relu)
// Assumes: A k-contiguous, B n-contiguous, M % 128 == 0, K % 16 == 0,
//          sAm % 4 == 0.  N guarded.
#define BM 128
#define BN 128
#define BK 16
#define BKP 20   // padded k-stride: 80B rows, 16B-aligned, ldmatrix conflict-free

__global__ __launch_bounds__(128)
void gemm_tc(const float* __restrict__ A, const float* __restrict__ B,
             float* __restrict__ C, const float* __restrict__ bias,
             int M, int N, int K,
             int sAm, int sBk, int sCm, int sCn,
             int HD, int sA1, int sA2, int sB1, int sB2, int sC1, int sC2,
             float alpha, int relu)
{
    const int z = blockIdx.z;
    A += (size_t)(z / HD) * sA1 + (size_t)(z % HD) * sA2;
    B += (size_t)(z / HD) * sB1 + (size_t)(z % HD) * sB2;
    C += (size_t)(z / HD) * sC1 + (size_t)(z % HD) * sC2;

    const int row0 = blockIdx.y * BM;
    const int col0 = blockIdx.x * BN;
    const int tid  = threadIdx.x;
    const int w    = tid >> 5;
    const int lane = tid & 31;
    const int wm   = w & 1;          // 2 warps over M (64 rows)
    const int wn   = w >> 1;         // 2 warps over N (64 cols)
    const int r    = lane >> 2;
    const int cq   = lane & 3;

    __shared__ __align__(16) uint32_t As[2][BM][BKP];
    __shared__ __align__(16) uint32_t Bs[2][BN][BKP];

    float acc[4][8][4];
#pragma unroll
    for (int i = 0; i < 4; i++)
#pragma unroll
        for (int j = 0; j < 8; j++)
#pragma unroll
            for (int q = 0; q < 4; q++) acc[i][j][q] = 0.f;

    // ---- ldmatrix per-lane geometry ----
    const int T  = lane >> 3;        // tile index 0..3
    const int ri = lane & 7;         // row within tile
    // A tiles: (rows +0/+8) x (k +0/+4):  row add = (T&1)*8, k add = (T>>1)*4
    const int aRowLane = (T & 1) * 8 + ri;
    const int aKadd    = (T >> 1) * 4;
    // B tiles: (n +0/+8) x (k +0/+4):    n add = (T>>1)*8, k add = (T&1)*4
    const int bColLane = (T >> 1) * 8 + ri;
    const int bKadd    = (T & 1) * 4;

    // ---- loader geometry ----
    const int arow = tid >> 2;            // 0..31 (A rows, 4 blocks of 32)
    const int ak4  = (tid & 3) * 4;       // k offset (float4)
    float4 a4s[4];
    float rB[16];
    const int gn  = col0 + tid;
    const bool okn = (gn < N);

    // ---- load tile 0 ----
#pragma unroll
    for (int rr = 0; rr < 4; rr++)
        a4s[rr] = *(const float4*)&A[(size_t)(row0 + arow + rr * 32) * sAm + ak4];
#pragma unroll
    for (int l = 0; l < 16; l++)
        rB[l] = okn ? B[(size_t)l * sBk + gn] : 0.f;

#pragma unroll
    for (int rr = 0; rr < 4; rr++) {
        uint4 u = make_uint4(f2tf32(a4s[rr].x), f2tf32(a4s[rr].y),
                             f2tf32(a4s[rr].z), f2tf32(a4s[rr].w));
        *(uint4*)&As[0][arow + rr * 32][ak4] = u;
    }
#pragma unroll
    for (int l = 0; l < 16; l++) Bs[0][tid][l] = f2tf32(rB[l]);
    __syncthreads();

    int cur = 0;
    for (int k0 = 0; k0 < K; k0 += BK) {
        const bool nxt = (k0 + BK) < K;
        if (nxt) {
            const int kn = k0 + BK;
#pragma unroll
            for (int rr = 0; rr < 4; rr++)
                a4s[rr] = *(const float4*)&A[(size_t)(row0 + arow + rr * 32) * sAm + kn + ak4];
#pragma unroll
            for (int l = 0; l < 16; l++)
                rB[l] = okn ? B[(size_t)(kn + l) * sBk + gn] : 0.f;
        }

        // ---- compute from smem buffer `cur` ----
        const uint32_t aBase = smem_u32(&As[cur][0][0]);
        const uint32_t bBase = smem_u32(&Bs[cur][0][0]);
#pragma unroll
        for (int k8 = 0; k8 < BK; k8 += 8) {
            uint32_t af[4][4];
            uint32_t bf[8][2];
            const uint32_t aK = aBase + (uint32_t)(k8 + aKadd) * 4;
#pragma unroll
            for (int mt = 0; mt < 4; mt++) {
                const uint32_t addr = aK + (uint32_t)(wm * 64 + mt * 16 + aRowLane) * 80;
                ldsm4(af[mt][0], af[mt][1], af[mt][2], af[mt][3], addr);
            }
            const uint32_t bK = bBase + (uint32_t)(k8 + bKadd) * 4;
#pragma unroll
            for (int p = 0; p < 4; p++) {
                const uint32_t addr = bK + (uint32_t)(wn * 64 + p * 16 + bColLane) * 80;
                ldsm4(bf[2 * p][0], bf[2 * p][1], bf[2 * p + 1][0], bf[2 * p + 1][1], addr);
            }
#pragma unroll
            for (int mt = 0; mt < 4; mt++)
#pragma unroll
                for (int nt = 0; nt < 8; nt++)
                    mma_tf32(acc[mt][nt], af[mt], bf[nt]);
        }

        if (nxt) {
            const int nb = cur ^ 1;
#pragma unroll
            for (int rr = 0; rr < 4; rr++) {
                uint4 u = make_uint4(f2tf32(a4s[rr].x), f2tf32(a4s[rr].y),
                                     f2tf32(a4s[rr].z), f2tf32(a4s[rr].w));
                *(uint4*)&As[nb][arow + rr * 32][ak4] = u;
            }
#pragma unroll
            for (int l = 0; l < 16; l++) Bs[nb][tid][l] = f2tf32(rB[l]);
            cur = nb;
            __syncthreads();
        }
    }

    // ---- epilogue ----
#pragma unroll
    for (int mt = 0; mt < 4; mt++) {
        const int rr0 = row0 + wm * 64 + mt * 16 + r;
        const int rr1 = rr0 + 8;
#pragma unroll
        for (int nt = 0; nt < 8; nt++) {
            const int cc0 = col0 + wn * 64 + nt * 8 + 2 * cq;
            const int cc1 = cc0 + 1;
            if (cc0 < N) {
                float v0 = acc[mt][nt][0] * alpha;
                float v2 = acc[mt][nt][2] * alpha;
                if (bias) { v0 += bias[cc0]; v2 += bias[cc0]; }
                if (relu) { v0 = fmaxf(v0, 0.f); v2 = fmaxf(v2, 0.f); }
                C[(size_t)rr0 * sCm + (size_t)cc0 * sCn] = v0;
                C[(size_t)rr1 * sCm + (size_t)cc0 * sCn] = v2;
            }
            if (cc1 < N) {
                float v1 = acc[mt][nt][1] * alpha;
                float v3 = acc[mt][nt][3] * alpha;
                if (bias) { v1 += bias[cc1]; v3 += bias[cc1]; }
                if (relu) { v1 = fmaxf(v1, 0.f); v3 = fmaxf(v3, 0.f); }
                C[(size_t)rr0 * sCm + (size_t)cc1 * sCn] = v1;
                C[(size_t)rr1 * sCm + (size_t)cc1 * sCn] = v3;
            }
        }
    }
}

// ---------------- softmax over rows of length 1024 --------------------------
__global__ __launch_bounds__(256)
void softmax_k(float* __restrict__ S)
{
    float4* p = (float4*)(S + (size_t)blockIdx.x * 1024);
    const int t = threadIdx.x;
    const int lane = t & 31, wid = t >> 5;
    __shared__ float red[8];

    float4 v = p[t];
    float m = fmaxf(fmaxf(v.x, v.y), fmaxf(v.z, v.w));
#pragma unroll
    for (int s = 16; s > 0; s >>= 1) m = fmaxf(m, __shfl_xor_sync(0xffffffffu, m, s));
    if (lane == 0) red[wid] = m;
    __syncthreads();
    m = red[lane & 7];
#pragma unroll
    for (int s = 4; s > 0; s >>= 1) m = fmaxf(m, __shfl_xor_sync(0xffffffffu, m, s));
    m = __shfl_sync(0xffffffffu, m, 0);

    v.x = __expf(v.x - m); v.y = __expf(v.y - m);
    v.z = __expf(v.z - m); v.w = __expf(v.w - m);
    float sum = v.x + v.y + v.z + v.w;
#pragma unroll
    for (int s = 16; s > 0; s >>= 1) sum += __shfl_xor_sync(0xffffffffu, sum, s);
    __syncthreads();
    if (lane == 0) red[wid] = sum;
    __syncthreads();
    sum = red[lane & 7];
#pragma unroll
    for (int s = 4; s > 0; s >>= 1) sum += __shfl_xor_sync(0xffffffffu, sum, s);
    sum = __shfl_sync(0xffffffffu, sum, 0);

    float inv = 1.f / sum;
    v.x *= inv; v.y *= inv; v.z *= inv; v.w *= inv;
    p[t] = v;
}

// ---------------- residual + layernorm (rows of 512) ------------------------
__global__ __launch_bounds__(256)
void ln_k(float* __restrict__ out, const float* __restrict__ a,
          const float* __restrict__ b, const float* __restrict__ gamma,
          const float* __restrict__ beta)
{
    size_t base = (size_t)blockIdx.x * DD;
    int t = threadIdx.x;
    float x0 = a[base + t]       + b[base + t];
    float x1 = a[base + t + 256] + b[base + t + 256];

    __shared__ float r1[256], r2[256];
    r1[t] = x0 + x1;
    r2[t] = x0 * x0 + x1 * x1;
    __syncthreads();
    for (int s = 128; s > 0; s >>= 1) {
        if (t < s) { r1[t] += r1[t + s]; r2[t] += r2[t + s]; }
        __syncthreads();
    }
    float mean = r1[0] * (1.f / DD);
    float var  = r2[0] * (1.f / DD) - mean * mean;
    float rstd = rsqrtf(var + LN_EPS);

    out[base + t]       = gamma[t]       * (x0 - mean) * rstd + beta[t];
    out[base + t + 256] = gamma[t + 256] * (x1 - mean) * rstd + beta[t + 256];
}

// ---------------- host side --------------------------------------------------
static void gemm(const float* A, const float* B, float* C, const float* bias,
                 int M, int N, int K, int nb, int HD,
                 int sAm, int sBk, int sCm, int sCn,
                 int sA1, int sA2, int sB1, int sB2, int sC1, int sC2,
                 float alpha, int relu)
{
    dim3 grid((N + BN - 1) / BN, (M + BM - 1) / BM, nb);
    gemm_tc<<<grid, 128>>>(A, B, C, bias, M, N, K,
                           sAm, sBk, sCm, sCn,
                           HD, sA1, sA2, sB1, sB2, sC1, sC2, alpha, relu);
}

extern "C" void kernel_launch(void* const* d_in, const int* in_sizes, int n_in,
                              void* d_out, int out_size)
{
    const float* x      = (const float*)d_in[0];
    const float* qw     = (const float*)d_in[1];
    const float* kw     = (const float*)d_in[2];
    const float* vw     = (const float*)d_in[3];
    const float* lw     = (const float*)d_in[4];
    const float* gamma1 = (const float*)d_in[5];
    const float* beta1  = (const float*)d_in[6];
    const float* w1     = (const float*)d_in[7];
    const float* b1     = (const float*)d_in[8];
    const float* w2     = (const float*)d_in[9];
    const float* b2     = (const float*)d_in[10];
    const float* gamma2 = (const float*)d_in[11];
    const float* beta2  = (const float*)d_in[12];
    float* out = (float*)d_out;

    float *q, *kT, *v, *scores, *concat, *tmp, *h, *ff;
    cudaGetSymbolAddress((void**)&q,      g_q);
    cudaGetSymbolAddress((void**)&kT,     g_kT);
    cudaGetSymbolAddress((void**)&v,      g_v);
    cudaGetSymbolAddress((void**)&scores, g_scores);
    cudaGetSymbolAddress((void**)&concat, g_concat);
    cudaGetSymbolAddress((void**)&tmp,    g_tmp);
    cudaGetSymbolAddress((void**)&h,      g_h);
    cudaGetSymbolAddress((void**)&ff,     g_ff);

    const float scale = 1.0f / sqrtf((float)DD);

    // batches z = h*B + b, HD = B: z/HD = head, z%HD = batch
    // 1) Q projection: [S,U] per (h,b)
    gemm(x, qw, q, nullptr, SS, UU, DD, HH * BB, BB,
         DD, UU, UU, 1,
         0, SS * DD,
         DD * UU, 0,
         BB * SS * UU, SS * UU,
         1.f, 0);

    // 2) K projection stored transposed: kT[h,b][u,s]
    gemm(x, kw, kT, nullptr, SS, UU, DD, HH * BB, BB,
         DD, UU, 1, SS,
         0, SS * DD,
         DD * UU, 0,
         BB * UU * SS, UU * SS,
         1.f, 0);

    // 3) V projection: [S,D] per (h,b)
    gemm(x, vw, v, nullptr, SS, DD, DD, HH * BB, BB,
         DD, DD, DD, 1,
         0, SS * DD,
         DD * DD, 0,
         BB * SS * DD, SS * DD,
         1.f, 0);

    // 4) scores = scale * Q @ K^T : [S,S] per (h,b)
    gemm(q, kT, scores, nullptr, SS, SS, UU, HH * BB, BB,
         UU, SS, SS, 1,
         BB * SS * UU, SS * UU,
         BB * UU * SS, UU * SS,
         BB * SS * SS, SS * SS,
         scale, 0);

    // 5) softmax rows
    softmax_k<<<HH * BB * SS, 256>>>(scores);

    // 6) attn = probs @ V, written straight into concat layout [B,S,H*D]
    gemm(scores, v, concat, nullptr, SS, DD, SS, HH * BB, BB,
         SS, DD, HH * DD, 1,
         BB * SS * SS, SS * SS,
         BB * SS * DD, SS * DD,
         DD, SS * HH * DD,
         1.f, 0);

    // 7) output projection: [B*S, 4096] @ [4096, 512]
    gemm(concat, lw, tmp, nullptr, BB * SS, DD, HH * DD, 1, 1,
         HH * DD, DD, DD, 1,
         0, 0, 0, 0, 0, 0,
         1.f, 0);

    // 8) h = LN(x + mha)
    ln_k<<<BB * SS, 256>>>(h, x, tmp, gamma1, beta1);

    // 9) ff = relu(h @ w1 + b1)
    gemm(h, w1, ff, b1, BB * SS, FF, DD, 1, 1,
         DD, FF, FF, 1,
         0, 0, 0, 0, 0, 0,
         1.f, 1);

    // 10) tmp = ff @ w2 + b2
    gemm(ff, w2, tmp, b2, BB * SS, DD, FF, 1, 1,
         FF, DD, DD, 1,
         0, 0, 0, 0, 0, 0,
         1.f, 0);

    // 11) out = LN(h + tmp)
    ln_k<<<BB * SS, 256>>>(out, h, tmp, gamma2, beta2);
}